// round 1
// baseline (speedup 1.0000x reference)
#include <cuda_runtime.h>

#define BB 256
#define TT 2048
#define HH 128
#define FC1N 64

__device__ __forceinline__ unsigned long long fma2(unsigned long long a,
                                                   unsigned long long b,
                                                   unsigned long long c) {
    unsigned long long d;
    asm("fma.rn.f32x2 %0, %1, %2, %3;" : "=l"(d) : "l"(a), "l"(b), "l"(c));
    return d;
}

__device__ __forceinline__ float2 unpack2(unsigned long long v) {
    float2 r;
    asm("mov.b64 {%0, %1}, %2;" : "=f"(r.x), "=f"(r.y) : "l"(v));
    return r;
}

__global__ __launch_bounds__(128, 2)
void rnn_fused_kernel(const float* __restrict__ x,
                      const float* __restrict__ hidden,
                      const float* __restrict__ W_ih,
                      const float* __restrict__ W_hh,
                      const float* __restrict__ b_ih,
                      const float* __restrict__ b_hh,
                      const float* __restrict__ W_fc1,
                      const float* __restrict__ b_fc1,
                      const float* __restrict__ W_fc2,
                      const float* __restrict__ b_fc2,
                      float* __restrict__ out)
{
    __shared__ __align__(16) float x_sh[TT * 3];      // 24 KB: this batch row's inputs
    __shared__ __align__(16) float h_sh[2][HH];       // double-buffered hidden state
    __shared__ float wc_sh[3][HH];                    // collapsed fc2@fc1

    const int b = blockIdx.x;
    const int j = threadIdx.x;          // hidden unit owned by this thread
    const int wid = j >> 5;
    const int lane = j & 31;

    // ---- preload x[b] into SMEM (coalesced float4) ----
    {
        const float4* xg = (const float4*)(x + (size_t)b * TT * 3);
        float4* xs = (float4*)x_sh;
        #pragma unroll
        for (int i = 0; i < (TT * 3 / 4) / HH; i++)   // 12 iters
            xs[i * HH + j] = xg[i * HH + j];
    }

    // ---- W_hh row j into registers as packed f32x2 pairs (128 regs) ----
    unsigned long long w[HH / 2];
    {
        const unsigned long long* wg = (const unsigned long long*)(W_hh + j * HH);
        #pragma unroll
        for (int i = 0; i < HH / 2; i++) w[i] = wg[i];
    }

    const float wih0 = W_ih[j * 3 + 0];
    const float wih1 = W_ih[j * 3 + 1];
    const float wih2 = W_ih[j * 3 + 2];
    const float bias = b_ih[j] + b_hh[j];

    // ---- collapse FC head: Wc[o][j] = sum_f W_fc2[o][f] * W_fc1[f][j] ----
    {
        float wc0 = 0.f, wc1 = 0.f, wc2 = 0.f;
        #pragma unroll 4
        for (int f = 0; f < FC1N; f++) {
            float v = W_fc1[f * HH + j];
            wc0 = fmaf(W_fc2[0 * FC1N + f], v, wc0);
            wc1 = fmaf(W_fc2[1 * FC1N + f], v, wc1);
            wc2 = fmaf(W_fc2[2 * FC1N + f], v, wc2);
        }
        wc_sh[0][j] = wc0; wc_sh[1][j] = wc1; wc_sh[2][j] = wc2;
    }

    // ---- initial hidden state ----
    h_sh[0][j] = hidden[b * HH + j];
    __syncthreads();

    // ---- FC per-warp registers (warps 0..2 own output channel wid) ----
    float fwc0 = 0.f, fwc1 = 0.f, fwc2 = 0.f, fwc3 = 0.f, fbc = 0.f;
    if (wid < 3) {
        fwc0 = wc_sh[wid][lane];
        fwc1 = wc_sh[wid][lane + 32];
        fwc2 = wc_sh[wid][lane + 64];
        fwc3 = wc_sh[wid][lane + 96];
        float s = 0.f;
        #pragma unroll 8
        for (int f = 0; f < FC1N; f++)
            s = fmaf(W_fc2[wid * FC1N + f], b_fc1[f], s);
        fbc = s + b_fc2[wid];
    }

    float* outb = out + (size_t)b * TT * 3;

    int buf = 0;
    float hn = 0.f;
    for (int t = 0; t < TT; t++) {
        // input projection (x broadcast from SMEM)
        const float xv0 = x_sh[3 * t + 0];
        const float xv1 = x_sh[3 * t + 1];
        const float xv2 = x_sh[3 * t + 2];
        float xp = fmaf(xv2, wih2, fmaf(xv1, wih1, fmaf(xv0, wih0, bias)));

        // 128-wide dot(W_row_j, h) via packed f32x2 FMAs, 4 accumulator chains
        const ulonglong2* hp = (const ulonglong2*)h_sh[buf];
        unsigned long long a0 = 0ull, a1 = 0ull, a2 = 0ull, a3 = 0ull;
        #pragma unroll
        for (int i = 0; i < 16; i++) {
            ulonglong2 ha = hp[2 * i];
            ulonglong2 hb = hp[2 * i + 1];
            a0 = fma2(w[4 * i + 0], ha.x, a0);
            a1 = fma2(w[4 * i + 1], ha.y, a1);
            a2 = fma2(w[4 * i + 2], hb.x, a2);
            a3 = fma2(w[4 * i + 3], hb.y, a3);
        }
        float2 f0 = unpack2(a0), f1 = unpack2(a1);
        float2 f2 = unpack2(a2), f3 = unpack2(a3);
        float dot = ((f0.x + f0.y) + (f1.x + f1.y)) +
                    ((f2.x + f2.y) + (f3.x + f3.y));

        hn = tanhf(xp + dot);
        h_sh[buf ^ 1][j] = hn;
        __syncthreads();

        // fused FC head: out[b][t][o] = Wc[o] . h_new + bc[o]  (warps 0..2)
        if (wid < 3) {
            const float* hb = h_sh[buf ^ 1];
            float p = fwc0 * hb[lane] + fwc1 * hb[lane + 32] +
                      fwc2 * hb[lane + 64] + fwc3 * hb[lane + 96];
            p += __shfl_down_sync(0xffffffffu, p, 16);
            p += __shfl_down_sync(0xffffffffu, p, 8);
            p += __shfl_down_sync(0xffffffffu, p, 4);
            p += __shfl_down_sync(0xffffffffu, p, 2);
            p += __shfl_down_sync(0xffffffffu, p, 1);
            if (lane == 0) outb[t * 3 + wid] = p + fbc;
        }
        buf ^= 1;
    }

    // final hidden state -> second output region
    out[(size_t)BB * TT * 3 + b * HH + j] = hn;
}

extern "C" void kernel_launch(void* const* d_in, const int* in_sizes, int n_in,
                              void* d_out, int out_size) {
    const float* x      = (const float*)d_in[0];
    const float* hidden = (const float*)d_in[1];
    const float* W_ih   = (const float*)d_in[2];
    const float* W_hh   = (const float*)d_in[3];
    const float* b_ih   = (const float*)d_in[4];
    const float* b_hh   = (const float*)d_in[5];
    const float* W_fc1  = (const float*)d_in[6];
    const float* b_fc1  = (const float*)d_in[7];
    const float* W_fc2  = (const float*)d_in[8];
    const float* b_fc2  = (const float*)d_in[9];
    float* out = (float*)d_out;

    rnn_fused_kernel<<<BB, HH>>>(x, hidden, W_ih, W_hh, b_ih, b_hh,
                                 W_fc1, b_fc1, W_fc2, b_fc2, out);
}